// round 13
// baseline (speedup 1.0000x reference)
#include <cuda_runtime.h>
#include <cuda_bf16.h>
#include <mma.h>

using namespace nvcuda;

#define N_NODES 262144
#define N_EDGES 1048576
#define N_GRAPHS 8192
#define H 128
#define H2 256
#define LAYERS 4
#define FA 9
#define VA 64
#define FB 3
#define VB 8

// ---------------- scratch ----------------------------------------------------
__device__ float g_h[(size_t)N_NODES * H];
__device__ float g_agg[(size_t)N_NODES * H];
__device__ float g_t[(size_t)N_NODES * H2];
__device__ float g_vn[(size_t)N_GRAPHS * H];
__device__ float g_pooled[(size_t)N_GRAPHS * H2];
// bf16x2 weights [K][N]
#define WT_L (32768 + 32768 + 65536 + 32768)   // 163840 per layer
__device__ __nv_bfloat16 g_w0[(size_t)LAYERS * WT_L];
__device__ __nv_bfloat16 g_w1[(size_t)LAYERS * WT_L];
// bf16x2 activation scratch
__device__ __nv_bfloat16 g_Z0[(size_t)N_NODES * H],  g_Z1[(size_t)N_NODES * H];
__device__ __nv_bfloat16 g_T0[(size_t)N_NODES * H2], g_T1[(size_t)N_NODES * H2];
__device__ __nv_bfloat16 g_H0[(size_t)N_NODES * H],  g_H1[(size_t)N_NODES * H];
__device__ __nv_bfloat16 g_V0[(size_t)N_GRAPHS * H], g_V1[(size_t)N_GRAPHS * H];
__device__ __nv_bfloat16 g_P0[(size_t)N_GRAPHS * H2],g_P1[(size_t)N_GRAPHS * H2];

__device__ __forceinline__ void split2(float v, __nv_bfloat16& o0, __nv_bfloat16& o1) {
    o0 = __float2bfloat16(v);
    o1 = __float2bfloat16(v - __bfloat162float(o0));
}

__device__ __forceinline__ void cp16(void* dst, const void* src) {
    unsigned d = (unsigned)__cvta_generic_to_shared(dst);
    asm volatile("cp.async.cg.shared.global [%0], [%1], 16;\n" :: "r"(d), "l"(src));
}

// ---- bf16x2 weight split ------------------------------------------------------
__global__ void wconv2_kernel(const float* __restrict__ W,
                              __nv_bfloat16* __restrict__ W0,
                              __nv_bfloat16* __restrict__ W1, int total) {
    int idx = blockIdx.x * blockDim.x + threadIdx.x;
    if (idx >= total) return;
    split2(W[idx], W0[idx], W1[idx]);
}

// ---- elementwise split of an f32 array -----------------------------------------
__global__ void split_plain_kernel(const float* __restrict__ src,
                                   __nv_bfloat16* __restrict__ D0,
                                   __nv_bfloat16* __restrict__ D1) {
    int idx = blockIdx.x * blockDim.x + threadIdx.x;   // total/4 threads
    float4 v = *(const float4*)(src + (size_t)idx * 4);
    __nv_bfloat16 a0[4], a1[4];
    split2(v.x, a0[0], a1[0]);
    split2(v.y, a0[1], a1[1]);
    split2(v.z, a0[2], a1[2]);
    split2(v.w, a0[3], a1[3]);
    *(uint2*)(D0 + (size_t)idx * 4) = *(uint2*)a0;
    *(uint2*)(D1 + (size_t)idx * 4) = *(uint2*)a1;
}

// ---- z = (1+eps)h + agg, split to bf16x2 ---------------------------------------
__global__ void split_z_kernel(const float* __restrict__ h,
                               const float* __restrict__ agg,
                               const float* __restrict__ epsp,
                               __nv_bfloat16* __restrict__ Z0,
                               __nv_bfloat16* __restrict__ Z1) {
    int idx = blockIdx.x * blockDim.x + threadIdx.x;   // N*H/4 threads
    float c0 = 1.0f + __ldg(epsp);
    float4 hv = *(const float4*)(h + (size_t)idx * 4);
    float4 gv = *(const float4*)(agg + (size_t)idx * 4);
    float z[4] = { fmaf(c0, hv.x, gv.x), fmaf(c0, hv.y, gv.y),
                   fmaf(c0, hv.z, gv.z), fmaf(c0, hv.w, gv.w) };
    __nv_bfloat16 a0[4], a1[4];
#pragma unroll
    for (int q = 0; q < 4; q++) split2(z[q], a0[q], a1[q]);
    *(uint2*)(Z0 + (size_t)idx * 4) = *(uint2*)a0;
    *(uint2*)(Z1 + (size_t)idx * 4) = *(uint2*)a1;
}

// ---------------- atom encoder ---------------------------------------------------
__global__ void atom_kernel(const int* __restrict__ x,
                            const float* __restrict__ emb,
                            float* __restrict__ h) {
    int idx = blockIdx.x * blockDim.x + threadIdx.x;
    int n = idx >> 5;
    int c = (idx & 31) << 2;
    float4 acc = make_float4(0.f, 0.f, 0.f, 0.f);
#pragma unroll
    for (int f = 0; f < FA; f++) {
        int v = x[n * FA + f];
        float4 e = *(const float4*)(emb + ((size_t)(f * VA + v) * H) + c);
        acc.x += e.x; acc.y += e.y; acc.z += e.z; acc.w += e.w;
    }
    *(float4*)(h + (size_t)n * H + c) = acc;
}

__global__ void vninit_kernel(const float* __restrict__ vn_emb,
                              float* __restrict__ vn) {
    int idx = blockIdx.x * blockDim.x + threadIdx.x;
    int g = idx >> 5;
    int c = (idx & 31) << 2;
    *(float4*)(vn + (size_t)g * H + c) = *(const float4*)(vn_emb + c);
}

__global__ void addvn_kernel(float* __restrict__ h,
                             const float* __restrict__ vn,
                             const int* __restrict__ batch,
                             float* __restrict__ agg) {
    int idx = blockIdx.x * blockDim.x + threadIdx.x;
    int n = idx >> 5;
    int c = (idx & 31) << 2;
    int g = batch[n];
    float4 hv = *(float4*)(h + (size_t)n * H + c);
    float4 vv = *(const float4*)(vn + (size_t)g * H + c);
    hv.x += vv.x; hv.y += vv.y; hv.z += vv.z; hv.w += vv.w;
    *(float4*)(h + (size_t)n * H + c) = hv;
    *(float4*)(agg + (size_t)n * H + c) = make_float4(0.f, 0.f, 0.f, 0.f);
}

__global__ void edge_kernel(const int* __restrict__ ei,
                            const int* __restrict__ ea,
                            const float* __restrict__ bond,
                            const float* __restrict__ h,
                            float* __restrict__ agg) {
    __shared__ float tab[FB * VB * H];
    for (int i = threadIdx.x; i < FB * VB * H; i += blockDim.x) tab[i] = bond[i];
    __syncthreads();
    int e = (blockIdx.x * blockDim.x + threadIdx.x) >> 5;
    int lane = threadIdx.x & 31;
    int src = ei[e];
    int dst = ei[N_EDGES + e];
    int a0 = ea[e * 3 + 0], a1 = ea[e * 3 + 1], a2 = ea[e * 3 + 2];
    int c = lane << 2;
    float4 hv = *(const float4*)(h + (size_t)src * H + c);
    float4 e0 = *(const float4*)(tab + (0 * VB + a0) * H + c);
    float4 e1 = *(const float4*)(tab + (1 * VB + a1) * H + c);
    float4 e2 = *(const float4*)(tab + (2 * VB + a2) * H + c);
    float m0 = fmaxf(hv.x + e0.x + e1.x + e2.x, 0.f);
    float m1 = fmaxf(hv.y + e0.y + e1.y + e2.y, 0.f);
    float m2 = fmaxf(hv.z + e0.z + e1.z + e2.z, 0.f);
    float m3 = fmaxf(hv.w + e0.w + e1.w + e2.w, 0.f);
    float* p = agg + (size_t)dst * H + c;
    atomicAdd(p + 0, m0);
    atomicAdd(p + 1, m1);
    atomicAdd(p + 2, m2);
    atomicAdd(p + 3, m3);
}

// ======== bf16x2 GEMM v5: 4 products, BK=64, conflict-free, double-buffered =====
// Tile 128M x 64N. 8 warps = 4m x 2n, warp tile 32x32.
// acc0 = A0B0; accR = A0B1 + A1B0 + A1B1   (full (A0+A1)(B0+B1) product)
// MODE_A: 0 = A from (A0g,A1g)[M,K]; 2 = concat(V[batch][G,128], A[M,128]).
#define BK 64
#define A_LD 72
#define B_LD 72
#define OFF_A0 0
#define OFF_A1 18432
#define OFF_B0 36864
#define OFF_B1 46080
#define STAGE  55296   // bytes per stage; x2 = 110592 (dynamic SMEM)

template <int MODE_A, bool BN_RELU, bool OUT_F32, bool OUT_SPLIT>
__global__ __launch_bounds__(256, 2) void gemm3(
    const __nv_bfloat16* __restrict__ A0g, const __nv_bfloat16* __restrict__ A1g,
    const __nv_bfloat16* __restrict__ V0g, const __nv_bfloat16* __restrict__ V1g,
    const int* __restrict__ batch,
    const __nv_bfloat16* __restrict__ W0, const __nv_bfloat16* __restrict__ W1,
    const float* __restrict__ bias,
    const float* __restrict__ bng, const float* __restrict__ bnb,
    const float* __restrict__ bnm, const float* __restrict__ bnv,
    float* __restrict__ Cf,
    __nv_bfloat16* __restrict__ C0, __nv_bfloat16* __restrict__ C1,
    int M, int K, int Ncol) {
    extern __shared__ __align__(16) char smem[];

    const int tid = threadIdx.x;
    const int wid = tid >> 5;
    const int wm = wid & 3;
    const int wn = wid >> 2;
    const int m0 = blockIdx.x * 128;
    const int n0 = blockIdx.y * 64;

    const int arow = tid >> 1;               // 0..127
    const int ak = (tid & 1) << 5;           // 0 or 32
    const int grow = m0 + arow;
    int bg = 0;
    if (MODE_A == 2) bg = batch[grow];

    wmma::fragment<wmma::accumulator, 16, 16, 16, float> acc0[2][2], accR[2][2];
#pragma unroll
    for (int mi = 0; mi < 2; mi++)
#pragma unroll
        for (int ni = 0; ni < 2; ni++) {
            wmma::fill_fragment(acc0[mi][ni], 0.0f);
            wmma::fill_fragment(accR[mi][ni], 0.0f);
        }

    auto stage = [&](int kt, int buf) {
        char* base = smem + buf * STAGE;
        int gk = kt * BK + ak;                // 32-elem chunk, never straddles H
        const __nv_bfloat16 *s0, *s1;
        if (MODE_A == 0) {
            size_t o = (size_t)grow * K + gk;
            s0 = A0g + o; s1 = A1g + o;
        } else {
            if (gk < H) {
                size_t o = (size_t)bg * H + gk;
                s0 = V0g + o; s1 = V1g + o;
            } else {
                size_t o = (size_t)grow * H + (gk - H);
                s0 = A0g + o; s1 = A1g + o;
            }
        }
        int soff = (arow * A_LD + ak) * 2;
#pragma unroll
        for (int q = 0; q < 4; q++) {
            cp16(base + OFF_A0 + soff + q * 16, s0 + q * 8);
            cp16(base + OFF_A1 + soff + q * 16, s1 + q * 8);
        }
        // B: 2 splits x 64 rows x 64 cols = 1024 16B-chunks, 4 per thread
#pragma unroll
        for (int c = tid; c < 1024; c += 256) {
            int sp = c >> 9, rem = c & 511, r = rem >> 3, ch = rem & 7;
            size_t go = (size_t)(kt * BK + r) * Ncol + n0 + ch * 8;
            const __nv_bfloat16* src = (sp == 0) ? (W0 + go) : (W1 + go);
            cp16(base + OFF_B0 + sp * 9216 + (r * B_LD + ch * 8) * 2, src);
        }
        asm volatile("cp.async.commit_group;\n" ::);
    };

    const int KT = K / BK;
    stage(0, 0);
    for (int kt = 0; kt < KT; kt++) {
        if (kt + 1 < KT) {
            stage(kt + 1, (kt + 1) & 1);
            asm volatile("cp.async.wait_group 1;\n" ::);
        } else {
            asm volatile("cp.async.wait_group 0;\n" ::);
        }
        __syncthreads();
        char* base = smem + (kt & 1) * STAGE;
        const __nv_bfloat16* Ab0 = (const __nv_bfloat16*)(base + OFF_A0);
        const __nv_bfloat16* Ab1 = (const __nv_bfloat16*)(base + OFF_A1);
        const __nv_bfloat16* Bb0 = (const __nv_bfloat16*)(base + OFF_B0);
        const __nv_bfloat16* Bb1 = (const __nv_bfloat16*)(base + OFF_B1);

#pragma unroll
        for (int kk = 0; kk < 4; kk++) {
            wmma::fragment<wmma::matrix_a, 16, 16, 16, __nv_bfloat16, wmma::row_major>
                a0[2], a1[2];
#pragma unroll
            for (int mi = 0; mi < 2; mi++) {
                int ao = (wm * 32 + mi * 16) * A_LD + kk * 16;
                wmma::load_matrix_sync(a0[mi], Ab0 + ao, A_LD);
                wmma::load_matrix_sync(a1[mi], Ab1 + ao, A_LD);
            }
#pragma unroll
            for (int ni = 0; ni < 2; ni++) {
                wmma::fragment<wmma::matrix_b, 16, 16, 16, __nv_bfloat16, wmma::row_major> b0, b1;
                int bo = (kk * 16) * B_LD + wn * 32 + ni * 16;
                wmma::load_matrix_sync(b0, Bb0 + bo, B_LD);
                wmma::load_matrix_sync(b1, Bb1 + bo, B_LD);
#pragma unroll
                for (int mi = 0; mi < 2; mi++) {
                    wmma::mma_sync(acc0[mi][ni], a0[mi], b0, acc0[mi][ni]);
                    wmma::mma_sync(accR[mi][ni], a0[mi], b1, accR[mi][ni]);
                    wmma::mma_sync(accR[mi][ni], a1[mi], b0, accR[mi][ni]);
                    wmma::mma_sync(accR[mi][ni], a1[mi], b1, accR[mi][ni]);
                }
            }
        }
        __syncthreads();
    }

    // park combined result in SMEM (aliases stage buffers; all reads done)
    float* Cs = (float*)smem;
#pragma unroll
    for (int mi = 0; mi < 2; mi++)
#pragma unroll
        for (int ni = 0; ni < 2; ni++) {
#pragma unroll
            for (int e = 0; e < acc0[mi][ni].num_elements; e++)
                acc0[mi][ni].x[e] += accR[mi][ni].x[e];
            wmma::store_matrix_sync(&Cs[(wm * 32 + mi * 16) * 64 + wn * 32 + ni * 16],
                                    acc0[mi][ni], 64, wmma::mem_row_major);
        }
    __syncthreads();

    const int erow = tid >> 1;
    const int ecb = (tid & 1) << 5;
    const size_t rowoff = (size_t)(m0 + erow) * Ncol;
#pragma unroll
    for (int j = 0; j < 32; j += 4) {
        float y[4];
#pragma unroll
        for (int q = 0; q < 4; q++) {
            int col = n0 + ecb + j + q;
            float v = Cs[erow * 64 + ecb + j + q];
            if (BN_RELU) {
                float s = __ldg(bng + col) * rsqrtf(__ldg(bnv + col) + 1e-5f);
                float off = (__ldg(bias + col) - __ldg(bnm + col)) * s + __ldg(bnb + col);
                y[q] = fmaxf(fmaf(v, s, off), 0.0f);
            } else {
                y[q] = v + __ldg(bias + col);
            }
        }
        size_t o = rowoff + n0 + ecb + j;
        if (OUT_F32)
            *(float4*)(Cf + o) = make_float4(y[0], y[1], y[2], y[3]);
        if (OUT_SPLIT) {
            __nv_bfloat16 s0[4], s1[4];
#pragma unroll
            for (int q = 0; q < 4; q++) split2(y[q], s0[q], s1[q]);
            *(uint2*)(C0 + o) = *(uint2*)s0;
            *(uint2*)(C1 + o) = *(uint2*)s1;
        }
    }
}

// ---------------- zero pooled -----------------------------------------------------
__global__ void zero_pooled_kernel(float4* __restrict__ p) {
    int idx = blockIdx.x * blockDim.x + threadIdx.x;
    p[idx] = make_float4(0.f, 0.f, 0.f, 0.f);
}

__global__ void pool_kernel(const float* __restrict__ t,
                            const int* __restrict__ batch,
                            float* __restrict__ pooled) {
    int idx = blockIdx.x * blockDim.x + threadIdx.x;
    int n = idx >> 6;
    int c = (idx & 63) << 2;
    int g = batch[n];
    float4 v = *(const float4*)(t + (size_t)n * H2 + c);
    float* p = pooled + (size_t)g * H2 + c;
    atomicAdd(p + 0, v.x);
    atomicAdd(p + 1, v.y);
    atomicAdd(p + 2, v.z);
    atomicAdd(p + 3, v.w);
}

__global__ void final_kernel(const float* __restrict__ vn,
                             const float* __restrict__ pW1,
                             const float* __restrict__ pb1,
                             const float* __restrict__ pW2,
                             const float* __restrict__ pb2,
                             float* __restrict__ out) {
    int g = blockIdx.x;
    int j = threadIdx.x;
    __shared__ float vrow[H];
    vrow[j] = vn[(size_t)g * H + j];
    __syncthreads();
    float acc = pb1[j];
#pragma unroll 8
    for (int k = 0; k < H; k++) acc = fmaf(vrow[k], __ldg(pW1 + k * H + j), acc);
    float val = fmaxf(acc, 0.0f) * __ldg(pW2 + j);
#pragma unroll
    for (int o = 16; o > 0; o >>= 1) val += __shfl_down_sync(0xffffffffu, val, o);
    __shared__ float part[4];
    if ((j & 31) == 0) part[j >> 5] = val;
    __syncthreads();
    if (j == 0) {
        float s = part[0] + part[1] + part[2] + part[3] + pb2[0];
        out[g] = fminf(fmaxf(s, 0.0f), 50.0f);
    }
}

// ---------------- launch -------------------------------------------------------------
extern "C" void kernel_launch(void* const* d_in, const int* in_sizes, int n_in,
                              void* d_out, int out_size) {
    const int* x          = (const int*)d_in[0];
    const int* edge_index = (const int*)d_in[1];
    const int* edge_attr  = (const int*)d_in[2];
    const int* batch      = (const int*)d_in[3];
    const float* atom_emb  = (const float*)d_in[4];
    const float* vn_emb    = (const float*)d_in[5];
    const float* bond_emb  = (const float*)d_in[6];
    const float* conv_eps  = (const float*)d_in[7];
    const float* conv_W1   = (const float*)d_in[8];
    const float* conv_b1   = (const float*)d_in[9];
    const float* conv_bn_g = (const float*)d_in[10];
    const float* conv_bn_b = (const float*)d_in[11];
    const float* conv_bn_m = (const float*)d_in[12];
    const float* conv_bn_v = (const float*)d_in[13];
    const float* conv_W2   = (const float*)d_in[14];
    const float* conv_b2   = (const float*)d_in[15];
    const float* vn1_W  = (const float*)d_in[16];
    const float* vn1_b  = (const float*)d_in[17];
    const float* vn1_g  = (const float*)d_in[18];
    const float* vn1_be = (const float*)d_in[19];
    const float* vn1_m  = (const float*)d_in[20];
    const float* vn1_v  = (const float*)d_in[21];
    const float* vn2_W  = (const float*)d_in[22];
    const float* vn2_b  = (const float*)d_in[23];
    const float* vn2_g  = (const float*)d_in[24];
    const float* vn2_be = (const float*)d_in[25];
    const float* vn2_m  = (const float*)d_in[26];
    const float* vn2_v  = (const float*)d_in[27];
    const float* pW1 = (const float*)d_in[28];
    const float* pb1 = (const float*)d_in[29];
    const float* pW2 = (const float*)d_in[30];
    const float* pb2 = (const float*)d_in[31];
    float* out = (float*)d_out;

    float *h, *agg, *t, *vn, *pooled;
    __nv_bfloat16 *w0, *w1;
    __nv_bfloat16 *sZ0, *sZ1, *sT0, *sT1, *sH0, *sH1, *sV0, *sV1, *sP0, *sP1;
    cudaGetSymbolAddress((void**)&h, g_h);
    cudaGetSymbolAddress((void**)&agg, g_agg);
    cudaGetSymbolAddress((void**)&t, g_t);
    cudaGetSymbolAddress((void**)&vn, g_vn);
    cudaGetSymbolAddress((void**)&pooled, g_pooled);
    cudaGetSymbolAddress((void**)&w0, g_w0);
    cudaGetSymbolAddress((void**)&w1, g_w1);
    cudaGetSymbolAddress((void**)&sZ0, g_Z0); cudaGetSymbolAddress((void**)&sZ1, g_Z1);
    cudaGetSymbolAddress((void**)&sT0, g_T0); cudaGetSymbolAddress((void**)&sT1, g_T1);
    cudaGetSymbolAddress((void**)&sH0, g_H0); cudaGetSymbolAddress((void**)&sH1, g_H1);
    cudaGetSymbolAddress((void**)&sV0, g_V0); cudaGetSymbolAddress((void**)&sV1, g_V1);
    cudaGetSymbolAddress((void**)&sP0, g_P0); cudaGetSymbolAddress((void**)&sP1, g_P1);

    // opt-in dynamic SMEM (110592 bytes) for the 4 gemm3 instantiations
    const int DSM = 2 * STAGE;
    cudaFuncSetAttribute(gemm3<0, true,  false, true >, cudaFuncAttributeMaxDynamicSharedMemorySize, DSM);
    cudaFuncSetAttribute(gemm3<0, false, true,  true >, cudaFuncAttributeMaxDynamicSharedMemorySize, DSM);
    cudaFuncSetAttribute(gemm3<2, true,  true,  false>, cudaFuncAttributeMaxDynamicSharedMemorySize, DSM);
    cudaFuncSetAttribute(gemm3<0, true,  true,  true >, cudaFuncAttributeMaxDynamicSharedMemorySize, DSM);

    const int OFF_W1 = 0;         // 128x256
    const int OFF_W2 = 32768;     // 256x128
    const int OFF_V1 = 65536;     // 256x256
    const int OFF_V2 = 131072;    // 256x128
    for (int i = 0; i < LAYERS; i++) {
        size_t off = (size_t)i * WT_L;
        wconv2_kernel<<<(H * H2 + 255) / 256, 256>>>(
            conv_W1 + (size_t)i * H * H2, w0 + off + OFF_W1, w1 + off + OFF_W1, H * H2);
        wconv2_kernel<<<(H2 * H + 255) / 256, 256>>>(
            conv_W2 + (size_t)i * H2 * H, w0 + off + OFF_W2, w1 + off + OFF_W2, H2 * H);
        wconv2_kernel<<<(H2 * H2 + 255) / 256, 256>>>(
            vn1_W + (size_t)i * H2 * H2, w0 + off + OFF_V1, w1 + off + OFF_V1, H2 * H2);
        wconv2_kernel<<<(H2 * H + 255) / 256, 256>>>(
            vn2_W + (size_t)i * H2 * H, w0 + off + OFF_V2, w1 + off + OFF_V2, H2 * H);
    }

    atom_kernel<<<(N_NODES * 32) / 256, 256>>>(x, atom_emb, h);
    vninit_kernel<<<(N_GRAPHS * 32) / 256, 256>>>(vn_emb, vn);
    split_plain_kernel<<<(N_GRAPHS * H / 4) / 256, 256>>>(vn, sV0, sV1);

    for (int i = 0; i < LAYERS; i++) {
        size_t off = (size_t)i * WT_L;
        addvn_kernel<<<(N_NODES * 32) / 256, 256>>>(h, vn, batch, agg);
        edge_kernel<<<N_EDGES / 8, 256>>>(edge_index, edge_attr,
                                          bond_emb + (size_t)i * FB * VB * H, h, agg);
        // z = (1+eps)h + agg  -> bf16x2
        split_z_kernel<<<(N_NODES * H / 4) / 256, 256>>>(h, agg, conv_eps + i, sZ0, sZ1);
        // conv1: T(splits) = relu(bn(z @ W1 + b1))   [N,256]
        gemm3<0, true, false, true><<<dim3(N_NODES / 128, 4), 256, DSM>>>(
            sZ0, sZ1, nullptr, nullptr, nullptr,
            w0 + off + OFF_W1, w1 + off + OFF_W1,
            conv_b1 + i * H2, conv_bn_g + i * H2, conv_bn_b + i * H2,
            conv_bn_m + i * H2, conv_bn_v + i * H2,
            nullptr, sT0, sT1, N_NODES, H, H2);
        // conv2: h = T @ W2 + b2  (emit f32 h + splits sH)  [N,128]
        gemm3<0, false, true, true><<<dim3(N_NODES / 128, 2), 256, DSM>>>(
            sT0, sT1, nullptr, nullptr, nullptr,
            w0 + off + OFF_W2, w1 + off + OFF_W2,
            conv_b2 + i * H, nullptr, nullptr, nullptr, nullptr,
            h, sH0, sH1, N_NODES, H2, H);
        // vn1: t = relu(bn(concat(vn[batch], h) @ V1 + b))  [N,256] (f32 only)
        gemm3<2, true, true, false><<<dim3(N_NODES / 128, 4), 256, DSM>>>(
            sH0, sH1, sV0, sV1, batch,
            w0 + off + OFF_V1, w1 + off + OFF_V1,
            vn1_b + i * H2, vn1_g + i * H2, vn1_be + i * H2,
            vn1_m + i * H2, vn1_v + i * H2,
            t, nullptr, nullptr, N_NODES, H2, H2);
        zero_pooled_kernel<<<(N_GRAPHS * H2 / 4) / 256, 256>>>((float4*)pooled);
        pool_kernel<<<(N_NODES * 64) / 256, 256>>>(t, batch, pooled);
        split_plain_kernel<<<(N_GRAPHS * H2 / 4) / 256, 256>>>(pooled, sP0, sP1);
        // vn2: vn = relu(bn(pooled @ V2 + b))  (emit f32 vn + splits sV)  [G,128]
        gemm3<0, true, true, true><<<dim3(N_GRAPHS / 128, 2), 256, DSM>>>(
            sP0, sP1, nullptr, nullptr, nullptr,
            w0 + off + OFF_V2, w1 + off + OFF_V2,
            vn2_b + i * H, vn2_g + i * H, vn2_be + i * H,
            vn2_m + i * H, vn2_v + i * H,
            vn, sV0, sV1, N_GRAPHS, H2, H);
    }
    final_kernel<<<N_GRAPHS, 128>>>(vn, pW1, pb1, pW2, pb2, out);
}

// round 14
// speedup vs baseline: 1.0534x; 1.0534x over previous
#include <cuda_runtime.h>
#include <cuda_bf16.h>
#include <mma.h>

using namespace nvcuda;

#define N_NODES 262144
#define N_EDGES 1048576
#define N_GRAPHS 8192
#define H 128
#define H2 256
#define LAYERS 4
#define FA 9
#define VA 64
#define FB 3
#define VB 8

// ---------------- scratch ----------------------------------------------------
__device__ float g_h[(size_t)N_NODES * H];
__device__ float g_agg[(size_t)N_NODES * H];
__device__ float g_vn[(size_t)N_GRAPHS * H];
__device__ float g_pooled[(size_t)N_GRAPHS * H2];
__device__ float g_gv[(size_t)N_GRAPHS * H2];      // vn@V1_top + crow
__device__ float g_crow[(size_t)LAYERS * H2];
// bf16x2 weights [K][N]: W1, W2, V2
#define WT_L (32768 + 32768 + 32768)   // 98304 per layer
__device__ __nv_bfloat16 g_w0[(size_t)LAYERS * WT_L];
__device__ __nv_bfloat16 g_w1[(size_t)LAYERS * WT_L];
// composed M2 = W2 @ V1_bot  [256,256] per layer (bf16x2)
__device__ __nv_bfloat16 g_m0[(size_t)LAYERS * H2 * H2];
__device__ __nv_bfloat16 g_m1[(size_t)LAYERS * H2 * H2];
// bf16x2 activation scratch
__device__ __nv_bfloat16 g_Z0[(size_t)N_NODES * H],  g_Z1[(size_t)N_NODES * H];
__device__ __nv_bfloat16 g_T0[(size_t)N_NODES * H2], g_T1[(size_t)N_NODES * H2];
__device__ __nv_bfloat16 g_P0[(size_t)N_GRAPHS * H2],g_P1[(size_t)N_GRAPHS * H2];

__device__ __forceinline__ void split2(float v, __nv_bfloat16& o0, __nv_bfloat16& o1) {
    o0 = __float2bfloat16(v);
    o1 = __float2bfloat16(v - __bfloat162float(o0));
}

__device__ __forceinline__ void cp16(void* dst, const void* src) {
    unsigned d = (unsigned)__cvta_generic_to_shared(dst);
    asm volatile("cp.async.cg.shared.global [%0], [%1], 16;\n" :: "r"(d), "l"(src));
}

// ---- bf16x2 weight split ------------------------------------------------------
__global__ void wconv2_kernel(const float* __restrict__ W,
                              __nv_bfloat16* __restrict__ W0,
                              __nv_bfloat16* __restrict__ W1, int total) {
    int idx = blockIdx.x * blockDim.x + threadIdx.x;
    if (idx >= total) return;
    split2(W[idx], W0[idx], W1[idx]);
}

// ---- M2[k][c] = sum_j W2[k][j] * V1[(128+j)][c], split to bf16x2 ---------------
__global__ void compose_kernel(const float* __restrict__ W2,
                               const float* __restrict__ V1,
                               __nv_bfloat16* __restrict__ M0,
                               __nv_bfloat16* __restrict__ M1) {
    int k = blockIdx.x;          // 0..255
    int c = threadIdx.x;         // 0..255
    __shared__ float wrow[H];
    if (c < H) wrow[c] = W2[k * H + c];
    __syncthreads();
    float acc = 0.f;
#pragma unroll 8
    for (int j = 0; j < H; j++) acc = fmaf(wrow[j], V1[(size_t)(H + j) * H2 + c], acc);
    split2(acc, M0[k * H2 + c], M1[k * H2 + c]);
}

// ---- crow[c] = vn1_b[c] + sum_j b2[j] * V1[(128+j)][c] --------------------------
__global__ void crow_kernel(const float* __restrict__ V1,
                            const float* __restrict__ b2,
                            const float* __restrict__ vn1_b,
                            float* __restrict__ crow) {
    int c = threadIdx.x;
    float acc = vn1_b[c];
#pragma unroll 8
    for (int j = 0; j < H; j++) acc = fmaf(b2[j], V1[(size_t)(H + j) * H2 + c], acc);
    crow[c] = acc;
}

// ---- gv = vn @ V1_top + crow   (fp32 SIMT, [G,256], K=128) ----------------------
__global__ __launch_bounds__(256) void gvn_kernel(
    const float* __restrict__ vn, const float* __restrict__ V1,
    const float* __restrict__ crow, float* __restrict__ gv) {
    __shared__ float As[16][64];
    __shared__ float Bs[16][64];
    const int tid = threadIdx.x;
    const int m0 = blockIdx.x * 64;
    const int n0 = blockIdx.y * 64;
    const int tr = tid >> 4, tc = tid & 15;
    const int am = tid & 63, ak = (tid >> 6) << 2;
    const int bn = (tid & 15) << 2, bk = tid >> 4;
    float acc[4][4];
#pragma unroll
    for (int i = 0; i < 4; i++)
#pragma unroll
        for (int j = 0; j < 4; j++) acc[i][j] = 0.f;
    for (int k0 = 0; k0 < H; k0 += 16) {
        float4 a4 = *(const float4*)(vn + (size_t)(m0 + am) * H + k0 + ak);
        As[ak + 0][am] = a4.x; As[ak + 1][am] = a4.y;
        As[ak + 2][am] = a4.z; As[ak + 3][am] = a4.w;
        *(float4*)(&Bs[bk][bn]) = *(const float4*)(V1 + (size_t)(k0 + bk) * H2 + n0 + bn);
        __syncthreads();
#pragma unroll
        for (int kk = 0; kk < 16; kk++) {
            float ar[4], br[4];
            *(float4*)ar = *(const float4*)(&As[kk][tr << 2]);
            *(float4*)br = *(const float4*)(&Bs[kk][tc << 2]);
#pragma unroll
            for (int i = 0; i < 4; i++)
#pragma unroll
                for (int j = 0; j < 4; j++) acc[i][j] = fmaf(ar[i], br[j], acc[i][j]);
        }
        __syncthreads();
    }
#pragma unroll
    for (int i = 0; i < 4; i++) {
        float4 v;
        float* vp = (float*)&v;
#pragma unroll
        for (int j = 0; j < 4; j++)
            vp[j] = acc[i][j] + __ldg(crow + n0 + (tc << 2) + j);
        *(float4*)(gv + (size_t)(m0 + (tr << 2) + i) * H2 + n0 + (tc << 2)) = v;
    }
}

// ---- elementwise split of an f32 array ------------------------------------------
__global__ void split_plain_kernel(const float* __restrict__ src,
                                   __nv_bfloat16* __restrict__ D0,
                                   __nv_bfloat16* __restrict__ D1) {
    int idx = blockIdx.x * blockDim.x + threadIdx.x;
    float4 v = *(const float4*)(src + (size_t)idx * 4);
    __nv_bfloat16 a0[4], a1[4];
    split2(v.x, a0[0], a1[0]);
    split2(v.y, a0[1], a1[1]);
    split2(v.z, a0[2], a1[2]);
    split2(v.w, a0[3], a1[3]);
    *(uint2*)(D0 + (size_t)idx * 4) = *(uint2*)a0;
    *(uint2*)(D1 + (size_t)idx * 4) = *(uint2*)a1;
}

// ---- z = (1+eps)h + agg, split to bf16x2 ----------------------------------------
__global__ void split_z_kernel(const float* __restrict__ h,
                               const float* __restrict__ agg,
                               const float* __restrict__ epsp,
                               __nv_bfloat16* __restrict__ Z0,
                               __nv_bfloat16* __restrict__ Z1) {
    int idx = blockIdx.x * blockDim.x + threadIdx.x;
    float c0 = 1.0f + __ldg(epsp);
    float4 hv = *(const float4*)(h + (size_t)idx * 4);
    float4 gvv = *(const float4*)(agg + (size_t)idx * 4);
    float z[4] = { fmaf(c0, hv.x, gvv.x), fmaf(c0, hv.y, gvv.y),
                   fmaf(c0, hv.z, gvv.z), fmaf(c0, hv.w, gvv.w) };
    __nv_bfloat16 a0[4], a1[4];
#pragma unroll
    for (int q = 0; q < 4; q++) split2(z[q], a0[q], a1[q]);
    *(uint2*)(Z0 + (size_t)idx * 4) = *(uint2*)a0;
    *(uint2*)(Z1 + (size_t)idx * 4) = *(uint2*)a1;
}

// ---------------- atom encoder -----------------------------------------------------
__global__ void atom_kernel(const int* __restrict__ x,
                            const float* __restrict__ emb,
                            float* __restrict__ h) {
    int idx = blockIdx.x * blockDim.x + threadIdx.x;
    int n = idx >> 5;
    int c = (idx & 31) << 2;
    float4 acc = make_float4(0.f, 0.f, 0.f, 0.f);
#pragma unroll
    for (int f = 0; f < FA; f++) {
        int v = x[n * FA + f];
        float4 e = *(const float4*)(emb + ((size_t)(f * VA + v) * H) + c);
        acc.x += e.x; acc.y += e.y; acc.z += e.z; acc.w += e.w;
    }
    *(float4*)(h + (size_t)n * H + c) = acc;
}

__global__ void vninit_kernel(const float* __restrict__ vn_emb,
                              float* __restrict__ vn) {
    int idx = blockIdx.x * blockDim.x + threadIdx.x;
    int g = idx >> 5;
    int c = (idx & 31) << 2;
    *(float4*)(vn + (size_t)g * H + c) = *(const float4*)(vn_emb + c);
}

__global__ void addvn_kernel(float* __restrict__ h,
                             const float* __restrict__ vn,
                             const int* __restrict__ batch,
                             float* __restrict__ agg) {
    int idx = blockIdx.x * blockDim.x + threadIdx.x;
    int n = idx >> 5;
    int c = (idx & 31) << 2;
    int g = batch[n];
    float4 hv = *(float4*)(h + (size_t)n * H + c);
    float4 vv = *(const float4*)(vn + (size_t)g * H + c);
    hv.x += vv.x; hv.y += vv.y; hv.z += vv.z; hv.w += vv.w;
    *(float4*)(h + (size_t)n * H + c) = hv;
    *(float4*)(agg + (size_t)n * H + c) = make_float4(0.f, 0.f, 0.f, 0.f);
}

__global__ void edge_kernel(const int* __restrict__ ei,
                            const int* __restrict__ ea,
                            const float* __restrict__ bond,
                            const float* __restrict__ h,
                            float* __restrict__ agg) {
    __shared__ float tab[FB * VB * H];
    for (int i = threadIdx.x; i < FB * VB * H; i += blockDim.x) tab[i] = bond[i];
    __syncthreads();
    int e = (blockIdx.x * blockDim.x + threadIdx.x) >> 5;
    int lane = threadIdx.x & 31;
    int src = ei[e];
    int dst = ei[N_EDGES + e];
    int a0 = ea[e * 3 + 0], a1 = ea[e * 3 + 1], a2 = ea[e * 3 + 2];
    int c = lane << 2;
    float4 hv = *(const float4*)(h + (size_t)src * H + c);
    float4 e0 = *(const float4*)(tab + (0 * VB + a0) * H + c);
    float4 e1 = *(const float4*)(tab + (1 * VB + a1) * H + c);
    float4 e2 = *(const float4*)(tab + (2 * VB + a2) * H + c);
    float m0 = fmaxf(hv.x + e0.x + e1.x + e2.x, 0.f);
    float m1 = fmaxf(hv.y + e0.y + e1.y + e2.y, 0.f);
    float m2 = fmaxf(hv.z + e0.z + e1.z + e2.z, 0.f);
    float m3 = fmaxf(hv.w + e0.w + e1.w + e2.w, 0.f);
    float* p = agg + (size_t)dst * H + c;
    atomicAdd(p + 0, m0);
    atomicAdd(p + 1, m1);
    atomicAdd(p + 2, m2);
    atomicAdd(p + 3, m3);
}

// ======== bf16x2 GEMM (R12 config: 3 products, BK=32) + fused pooling ============
// Tile 128M x 64N. 8 warps = 4m x 2n, warp tile 32x32.
// acc0 = A0B0; accR = A0B1 + A1B0.
// POOL: y = relu((acc + gv[batch[row]][col])*s + (bnb - bnm*s)); atomicAdd pooled.
#define BK 32
#define A_LD 40
#define B_LD 72
#define OFF_A0 0
#define OFF_A1 10240
#define OFF_B0 20480
#define OFF_B1 25088
#define STAGE  29696   // bytes per stage; x2 = 59392 (dynamic SMEM)

template <bool BN_RELU, bool OUT_F32, bool OUT_SPLIT, bool POOL>
__global__ __launch_bounds__(256, 2) void gemm3(
    const __nv_bfloat16* __restrict__ A0g, const __nv_bfloat16* __restrict__ A1g,
    const __nv_bfloat16* __restrict__ W0, const __nv_bfloat16* __restrict__ W1,
    const float* __restrict__ bias,
    const float* __restrict__ bng, const float* __restrict__ bnb,
    const float* __restrict__ bnm, const float* __restrict__ bnv,
    float* __restrict__ Cf,
    __nv_bfloat16* __restrict__ C0, __nv_bfloat16* __restrict__ C1,
    const float* __restrict__ gv, const int* __restrict__ batch,
    float* __restrict__ pooled,
    int M, int K, int Ncol) {
    extern __shared__ __align__(16) char smem[];

    const int tid = threadIdx.x;
    const int wid = tid >> 5;
    const int wm = wid & 3;
    const int wn = wid >> 2;
    const int m0 = blockIdx.x * 128;
    const int n0 = blockIdx.y * 64;

    const int arow = tid >> 1;
    const int ak = (tid & 1) << 4;
    const int grow = m0 + arow;

    wmma::fragment<wmma::accumulator, 16, 16, 16, float> acc0[2][2], accR[2][2];
#pragma unroll
    for (int mi = 0; mi < 2; mi++)
#pragma unroll
        for (int ni = 0; ni < 2; ni++) {
            wmma::fill_fragment(acc0[mi][ni], 0.0f);
            wmma::fill_fragment(accR[mi][ni], 0.0f);
        }

    auto stage = [&](int kt, int buf) {
        char* base = smem + buf * STAGE;
        int gk = kt * BK + ak;
        size_t o = (size_t)grow * K + gk;
        int soff = (arow * A_LD + ak) * 2;
        cp16(base + OFF_A0 + soff, A0g + o);
        cp16(base + OFF_A0 + soff + 16, A0g + o + 8);
        cp16(base + OFF_A1 + soff, A1g + o);
        cp16(base + OFF_A1 + soff + 16, A1g + o + 8);
#pragma unroll
        for (int c = tid; c < 512; c += 256) {
            int sp = c >> 8, rem = c & 255, r = rem >> 3, ch = rem & 7;
            size_t go = (size_t)(kt * BK + r) * Ncol + n0 + ch * 8;
            const __nv_bfloat16* src = (sp == 0) ? (W0 + go) : (W1 + go);
            cp16(base + OFF_B0 + sp * 4608 + (r * B_LD + ch * 8) * 2, src);
        }
        asm volatile("cp.async.commit_group;\n" ::);
    };

    const int KT = K / BK;
    stage(0, 0);
    for (int kt = 0; kt < KT; kt++) {
        if (kt + 1 < KT) {
            stage(kt + 1, (kt + 1) & 1);
            asm volatile("cp.async.wait_group 1;\n" ::);
        } else {
            asm volatile("cp.async.wait_group 0;\n" ::);
        }
        __syncthreads();
        char* base = smem + (kt & 1) * STAGE;
        const __nv_bfloat16* Ab0 = (const __nv_bfloat16*)(base + OFF_A0);
        const __nv_bfloat16* Ab1 = (const __nv_bfloat16*)(base + OFF_A1);
        const __nv_bfloat16* Bb0 = (const __nv_bfloat16*)(base + OFF_B0);
        const __nv_bfloat16* Bb1 = (const __nv_bfloat16*)(base + OFF_B1);

#pragma unroll
        for (int kk = 0; kk < 2; kk++) {
            wmma::fragment<wmma::matrix_a, 16, 16, 16, __nv_bfloat16, wmma::row_major>
                a0[2], a1[2];
#pragma unroll
            for (int mi = 0; mi < 2; mi++) {
                int ao = (wm * 32 + mi * 16) * A_LD + kk * 16;
                wmma::load_matrix_sync(a0[mi], Ab0 + ao, A_LD);
                wmma::load_matrix_sync(a1[mi], Ab1 + ao, A_LD);
            }
#pragma unroll
            for (int ni = 0; ni < 2; ni++) {
                wmma::fragment<wmma::matrix_b, 16, 16, 16, __nv_bfloat16, wmma::row_major> b0, b1;
                int bo = (kk * 16) * B_LD + wn * 32 + ni * 16;
                wmma::load_matrix_sync(b0, Bb0 + bo, B_LD);
                wmma::load_matrix_sync(b1, Bb1 + bo, B_LD);
#pragma unroll
                for (int mi = 0; mi < 2; mi++) {
                    wmma::mma_sync(acc0[mi][ni], a0[mi], b0, acc0[mi][ni]);
                    wmma::mma_sync(accR[mi][ni], a0[mi], b1, accR[mi][ni]);
                    wmma::mma_sync(accR[mi][ni], a1[mi], b0, accR[mi][ni]);
                }
            }
        }
        __syncthreads();
    }

    float* Cs = (float*)smem;
#pragma unroll
    for (int mi = 0; mi < 2; mi++)
#pragma unroll
        for (int ni = 0; ni < 2; ni++) {
#pragma unroll
            for (int e = 0; e < acc0[mi][ni].num_elements; e++)
                acc0[mi][ni].x[e] += accR[mi][ni].x[e];
            wmma::store_matrix_sync(&Cs[(wm * 32 + mi * 16) * 64 + wn * 32 + ni * 16],
                                    acc0[mi][ni], 64, wmma::mem_row_major);
        }
    __syncthreads();

    const int erow = tid >> 1;
    const int ecb = (tid & 1) << 5;
    int bg = 0;
    const float* gvrow = nullptr;
    if (POOL) {
        bg = batch[m0 + erow];
        gvrow = gv + (size_t)bg * H2;
    }
    const size_t rowoff = (size_t)(m0 + erow) * Ncol;
#pragma unroll
    for (int j = 0; j < 32; j += 4) {
        float y[4];
#pragma unroll
        for (int q = 0; q < 4; q++) {
            int col = n0 + ecb + j + q;
            float v = Cs[erow * 64 + ecb + j + q];
            if (POOL) {
                float s = __ldg(bng + col) * rsqrtf(__ldg(bnv + col) + 1e-5f);
                float off = __ldg(bnb + col) - __ldg(bnm + col) * s;
                y[q] = fmaxf(fmaf(v + __ldg(gvrow + col), s, off), 0.0f);
            } else if (BN_RELU) {
                float s = __ldg(bng + col) * rsqrtf(__ldg(bnv + col) + 1e-5f);
                float off = (__ldg(bias + col) - __ldg(bnm + col)) * s + __ldg(bnb + col);
                y[q] = fmaxf(fmaf(v, s, off), 0.0f);
            } else {
                y[q] = v + __ldg(bias + col);
            }
        }
        if (POOL) {
            float* p = pooled + (size_t)bg * H2 + n0 + ecb + j;
            atomicAdd(p + 0, y[0]);
            atomicAdd(p + 1, y[1]);
            atomicAdd(p + 2, y[2]);
            atomicAdd(p + 3, y[3]);
        } else {
            size_t o = rowoff + n0 + ecb + j;
            if (OUT_F32)
                *(float4*)(Cf + o) = make_float4(y[0], y[1], y[2], y[3]);
            if (OUT_SPLIT) {
                __nv_bfloat16 s0[4], s1[4];
#pragma unroll
                for (int q = 0; q < 4; q++) split2(y[q], s0[q], s1[q]);
                *(uint2*)(C0 + o) = *(uint2*)s0;
                *(uint2*)(C1 + o) = *(uint2*)s1;
            }
        }
    }
}

// ---------------- zero pooled -------------------------------------------------------
__global__ void zero_pooled_kernel(float4* __restrict__ p) {
    int idx = blockIdx.x * blockDim.x + threadIdx.x;
    p[idx] = make_float4(0.f, 0.f, 0.f, 0.f);
}

__global__ void final_kernel(const float* __restrict__ vn,
                             const float* __restrict__ pW1,
                             const float* __restrict__ pb1,
                             const float* __restrict__ pW2,
                             const float* __restrict__ pb2,
                             float* __restrict__ out) {
    int g = blockIdx.x;
    int j = threadIdx.x;
    __shared__ float vrow[H];
    vrow[j] = vn[(size_t)g * H + j];
    __syncthreads();
    float acc = pb1[j];
#pragma unroll 8
    for (int k = 0; k < H; k++) acc = fmaf(vrow[k], __ldg(pW1 + k * H + j), acc);
    float val = fmaxf(acc, 0.0f) * __ldg(pW2 + j);
#pragma unroll
    for (int o = 16; o > 0; o >>= 1) val += __shfl_down_sync(0xffffffffu, val, o);
    __shared__ float part[4];
    if ((j & 31) == 0) part[j >> 5] = val;
    __syncthreads();
    if (j == 0) {
        float s = part[0] + part[1] + part[2] + part[3] + pb2[0];
        out[g] = fminf(fmaxf(s, 0.0f), 50.0f);
    }
}

// ---------------- launch ---------------------------------------------------------------
extern "C" void kernel_launch(void* const* d_in, const int* in_sizes, int n_in,
                              void* d_out, int out_size) {
    const int* x          = (const int*)d_in[0];
    const int* edge_index = (const int*)d_in[1];
    const int* edge_attr  = (const int*)d_in[2];
    const int* batch      = (const int*)d_in[3];
    const float* atom_emb  = (const float*)d_in[4];
    const float* vn_emb    = (const float*)d_in[5];
    const float* bond_emb  = (const float*)d_in[6];
    const float* conv_eps  = (const float*)d_in[7];
    const float* conv_W1   = (const float*)d_in[8];
    const float* conv_b1   = (const float*)d_in[9];
    const float* conv_bn_g = (const float*)d_in[10];
    const float* conv_bn_b = (const float*)d_in[11];
    const float* conv_bn_m = (const float*)d_in[12];
    const float* conv_bn_v = (const float*)d_in[13];
    const float* conv_W2   = (const float*)d_in[14];
    const float* conv_b2   = (const float*)d_in[15];
    const float* vn1_W  = (const float*)d_in[16];
    const float* vn1_b  = (const float*)d_in[17];
    const float* vn1_g  = (const float*)d_in[18];
    const float* vn1_be = (const float*)d_in[19];
    const float* vn1_m  = (const float*)d_in[20];
    const float* vn1_v  = (const float*)d_in[21];
    const float* vn2_W  = (const float*)d_in[22];
    const float* vn2_b  = (const float*)d_in[23];
    const float* vn2_g  = (const float*)d_in[24];
    const float* vn2_be = (const float*)d_in[25];
    const float* vn2_m  = (const float*)d_in[26];
    const float* vn2_v  = (const float*)d_in[27];
    const float* pW1 = (const float*)d_in[28];
    const float* pb1 = (const float*)d_in[29];
    const float* pW2 = (const float*)d_in[30];
    const float* pb2 = (const float*)d_in[31];
    float* out = (float*)d_out;

    float *h, *agg, *vn, *pooled, *gv, *crow;
    __nv_bfloat16 *w0, *w1, *m0p, *m1p;
    __nv_bfloat16 *sZ0, *sZ1, *sT0, *sT1, *sP0, *sP1;
    cudaGetSymbolAddress((void**)&h, g_h);
    cudaGetSymbolAddress((void**)&agg, g_agg);
    cudaGetSymbolAddress((void**)&vn, g_vn);
    cudaGetSymbolAddress((void**)&pooled, g_pooled);
    cudaGetSymbolAddress((void**)&gv, g_gv);
    cudaGetSymbolAddress((void**)&crow, g_crow);
    cudaGetSymbolAddress((void**)&w0, g_w0);
    cudaGetSymbolAddress((void**)&w1, g_w1);
    cudaGetSymbolAddress((void**)&m0p, g_m0);
    cudaGetSymbolAddress((void**)&m1p, g_m1);
    cudaGetSymbolAddress((void**)&sZ0, g_Z0); cudaGetSymbolAddress((void**)&sZ1, g_Z1);
    cudaGetSymbolAddress((void**)&sT0, g_T0); cudaGetSymbolAddress((void**)&sT1, g_T1);
    cudaGetSymbolAddress((void**)&sP0, g_P0); cudaGetSymbolAddress((void**)&sP1, g_P1);

    const int DSM = 2 * STAGE;
    cudaFuncSetAttribute(gemm3<true,  false, true,  false>, cudaFuncAttributeMaxDynamicSharedMemorySize, DSM);
    cudaFuncSetAttribute(gemm3<false, true,  false, false>, cudaFuncAttributeMaxDynamicSharedMemorySize, DSM);
    cudaFuncSetAttribute(gemm3<true,  false, false, true >, cudaFuncAttributeMaxDynamicSharedMemorySize, DSM);
    cudaFuncSetAttribute(gemm3<true,  true,  false, false>, cudaFuncAttributeMaxDynamicSharedMemorySize, DSM);

    const int OFF_W1 = 0;        // 128x256
    const int OFF_W2 = 32768;    // 256x128
    const int OFF_V2 = 65536;    // 256x128
    for (int i = 0; i < LAYERS; i++) {
        size_t off = (size_t)i * WT_L;
        wconv2_kernel<<<(H * H2 + 255) / 256, 256>>>(
            conv_W1 + (size_t)i * H * H2, w0 + off + OFF_W1, w1 + off + OFF_W1, H * H2);
        wconv2_kernel<<<(H2 * H + 255) / 256, 256>>>(
            conv_W2 + (size_t)i * H2 * H, w0 + off + OFF_W2, w1 + off + OFF_W2, H2 * H);
        wconv2_kernel<<<(H2 * H + 255) / 256, 256>>>(
            vn2_W + (size_t)i * H2 * H, w0 + off + OFF_V2, w1 + off + OFF_V2, H2 * H);
        // composed M2 and crow
        compose_kernel<<<H2, H2>>>(conv_W2 + (size_t)i * H2 * H,
                                   vn1_W + (size_t)i * H2 * H2,
                                   m0p + (size_t)i * H2 * H2, m1p + (size_t)i * H2 * H2);
        crow_kernel<<<1, H2>>>(vn1_W + (size_t)i * H2 * H2, conv_b2 + i * H,
                               vn1_b + i * H2, crow + (size_t)i * H2);
    }

    atom_kernel<<<(N_NODES * 32) / 256, 256>>>(x, atom_emb, h);
    vninit_kernel<<<(N_GRAPHS * 32) / 256, 256>>>(vn_emb, vn);

    for (int i = 0; i < LAYERS; i++) {
        size_t off = (size_t)i * WT_L;
        addvn_kernel<<<(N_NODES * 32) / 256, 256>>>(h, vn, batch, agg);
        edge_kernel<<<N_EDGES / 8, 256>>>(edge_index, edge_attr,
                                          bond_emb + (size_t)i * FB * VB * H, h, agg);
        // z = (1+eps)h + agg  -> bf16x2
        split_z_kernel<<<(N_NODES * H / 4) / 256, 256>>>(h, agg, conv_eps + i, sZ0, sZ1);
        // conv1: T(splits) = relu(bn(z @ W1 + b1))   [N,256]
        gemm3<true, false, true, false><<<dim3(N_NODES / 128, 4), 256, DSM>>>(
            sZ0, sZ1, w0 + off + OFF_W1, w1 + off + OFF_W1,
            conv_b1 + i * H2, conv_bn_g + i * H2, conv_bn_b + i * H2,
            conv_bn_m + i * H2, conv_bn_v + i * H2,
            nullptr, sT0, sT1, nullptr, nullptr, nullptr, N_NODES, H, H2);
        // conv2: h = T @ W2 + b2  (f32 only)          [N,128]
        gemm3<false, true, false, false><<<dim3(N_NODES / 128, 2), 256, DSM>>>(
            sT0, sT1, w0 + off + OFF_W2, w1 + off + OFF_W2,
            conv_b2 + i * H, nullptr, nullptr, nullptr, nullptr,
            h, nullptr, nullptr, nullptr, nullptr, nullptr, N_NODES, H2, H);
        // gv = vn @ V1_top + crow                      [G,256]
        gvn_kernel<<<dim3(N_GRAPHS / 64, H2 / 64), 256>>>(
            vn, vn1_W + (size_t)i * H2 * H2, crow + (size_t)i * H2, gv);
        // pooled = segsum(relu(bn(T@M2 + gv[batch])))   (fused vn1 + pool)
        zero_pooled_kernel<<<(N_GRAPHS * H2 / 4) / 256, 256>>>((float4*)pooled);
        gemm3<true, false, false, true><<<dim3(N_NODES / 128, 4), 256, DSM>>>(
            sT0, sT1, m0p + (size_t)i * H2 * H2, m1p + (size_t)i * H2 * H2,
            nullptr, vn1_g + i * H2, vn1_be + i * H2, vn1_m + i * H2, vn1_v + i * H2,
            nullptr, nullptr, nullptr, gv, batch, pooled, N_NODES, H2, H2);
        // split pooled, then vn2: vn = relu(bn(pooled @ V2 + b))  [G,128] f32 only
        split_plain_kernel<<<(N_GRAPHS * H2 / 4) / 256, 256>>>(pooled, sP0, sP1);
        gemm3<true, true, false, false><<<dim3(N_GRAPHS / 128, 2), 256, DSM>>>(
            sP0, sP1, w0 + off + OFF_V2, w1 + off + OFF_V2,
            vn2_b + i * H, vn2_g + i * H, vn2_be + i * H, vn2_m + i * H, vn2_v + i * H,
            vn, nullptr, nullptr, nullptr, nullptr, nullptr, N_GRAPHS, H2, H);
    }
    final_kernel<<<N_GRAPHS, 128>>>(vn, pW1, pb1, pW2, pb2, out);
}

// round 15
// speedup vs baseline: 1.3215x; 1.2546x over previous
#include <cuda_runtime.h>
#include <cuda_bf16.h>
#include <mma.h>

using namespace nvcuda;

#define N_NODES 262144
#define N_EDGES 1048576
#define N_GRAPHS 8192
#define H 128
#define H2 256
#define LAYERS 4
#define FA 9
#define VA 64
#define FB 3
#define VB 8

// ---------------- scratch ----------------------------------------------------
__device__ float g_h[(size_t)N_NODES * H];
__device__ float g_agg[(size_t)N_NODES * H];
__device__ float g_vn[(size_t)N_GRAPHS * H];
__device__ float g_pooled[(size_t)N_GRAPHS * H2];
__device__ float g_gv[(size_t)N_GRAPHS * H2];      // vn@V1_top + crow
__device__ float g_crow[(size_t)LAYERS * H2];
// bf16x2 weights [K][N]: W1, W2, V2
#define WT_L (32768 + 32768 + 32768)   // 98304 per layer
__device__ __nv_bfloat16 g_w0[(size_t)LAYERS * WT_L];
__device__ __nv_bfloat16 g_w1[(size_t)LAYERS * WT_L];
// composed M2 = W2 @ V1_bot  [256,256] per layer (bf16x2)
__device__ __nv_bfloat16 g_m0[(size_t)LAYERS * H2 * H2];
__device__ __nv_bfloat16 g_m1[(size_t)LAYERS * H2 * H2];
// bf16x2 activation scratch
__device__ __nv_bfloat16 g_Z0[(size_t)N_NODES * H],  g_Z1[(size_t)N_NODES * H];
__device__ __nv_bfloat16 g_T0[(size_t)N_NODES * H2], g_T1[(size_t)N_NODES * H2];
__device__ __nv_bfloat16 g_P0[(size_t)N_GRAPHS * H2],g_P1[(size_t)N_GRAPHS * H2];

__device__ __forceinline__ void split2(float v, __nv_bfloat16& o0, __nv_bfloat16& o1) {
    o0 = __float2bfloat16(v);
    o1 = __float2bfloat16(v - __bfloat162float(o0));
}

__device__ __forceinline__ void cp16(void* dst, const void* src) {
    unsigned d = (unsigned)__cvta_generic_to_shared(dst);
    asm volatile("cp.async.cg.shared.global [%0], [%1], 16;\n" :: "r"(d), "l"(src));
}

__device__ __forceinline__ void red4(float* p, float a, float b, float c, float d) {
    asm volatile("red.global.add.v4.f32 [%0], {%1, %2, %3, %4};"
                 :: "l"(p), "f"(a), "f"(b), "f"(c), "f"(d) : "memory");
}

// ---- bf16x2 weight split ------------------------------------------------------
__global__ void wconv2_kernel(const float* __restrict__ W,
                              __nv_bfloat16* __restrict__ W0,
                              __nv_bfloat16* __restrict__ W1, int total) {
    int idx = blockIdx.x * blockDim.x + threadIdx.x;
    if (idx >= total) return;
    split2(W[idx], W0[idx], W1[idx]);
}

// ---- M2[k][c] = sum_j W2[k][j] * V1[(128+j)][c], split to bf16x2 ---------------
__global__ void compose_kernel(const float* __restrict__ W2,
                               const float* __restrict__ V1,
                               __nv_bfloat16* __restrict__ M0,
                               __nv_bfloat16* __restrict__ M1) {
    int k = blockIdx.x;
    int c = threadIdx.x;
    __shared__ float wrow[H];
    if (c < H) wrow[c] = W2[k * H + c];
    __syncthreads();
    float acc = 0.f;
#pragma unroll 8
    for (int j = 0; j < H; j++) acc = fmaf(wrow[j], V1[(size_t)(H + j) * H2 + c], acc);
    split2(acc, M0[k * H2 + c], M1[k * H2 + c]);
}

// ---- crow[c] = vn1_b[c] + sum_j b2[j] * V1[(128+j)][c] --------------------------
__global__ void crow_kernel(const float* __restrict__ V1,
                            const float* __restrict__ b2,
                            const float* __restrict__ vn1_b,
                            float* __restrict__ crow) {
    int c = threadIdx.x;
    float acc = vn1_b[c];
#pragma unroll 8
    for (int j = 0; j < H; j++) acc = fmaf(b2[j], V1[(size_t)(H + j) * H2 + c], acc);
    crow[c] = acc;
}

// ---- gv = vn @ V1_top + crow   (fp32 SIMT, [G,256], K=128) ----------------------
__global__ __launch_bounds__(256) void gvn_kernel(
    const float* __restrict__ vn, const float* __restrict__ V1,
    const float* __restrict__ crow, float* __restrict__ gv) {
    __shared__ float As[16][64];
    __shared__ float Bs[16][64];
    const int tid = threadIdx.x;
    const int m0 = blockIdx.x * 64;
    const int n0 = blockIdx.y * 64;
    const int tr = tid >> 4, tc = tid & 15;
    const int am = tid & 63, ak = (tid >> 6) << 2;
    const int bn = (tid & 15) << 2, bk = tid >> 4;
    float acc[4][4];
#pragma unroll
    for (int i = 0; i < 4; i++)
#pragma unroll
        for (int j = 0; j < 4; j++) acc[i][j] = 0.f;
    for (int k0 = 0; k0 < H; k0 += 16) {
        float4 a4 = *(const float4*)(vn + (size_t)(m0 + am) * H + k0 + ak);
        As[ak + 0][am] = a4.x; As[ak + 1][am] = a4.y;
        As[ak + 2][am] = a4.z; As[ak + 3][am] = a4.w;
        *(float4*)(&Bs[bk][bn]) = *(const float4*)(V1 + (size_t)(k0 + bk) * H2 + n0 + bn);
        __syncthreads();
#pragma unroll
        for (int kk = 0; kk < 16; kk++) {
            float ar[4], br[4];
            *(float4*)ar = *(const float4*)(&As[kk][tr << 2]);
            *(float4*)br = *(const float4*)(&Bs[kk][tc << 2]);
#pragma unroll
            for (int i = 0; i < 4; i++)
#pragma unroll
                for (int j = 0; j < 4; j++) acc[i][j] = fmaf(ar[i], br[j], acc[i][j]);
        }
        __syncthreads();
    }
#pragma unroll
    for (int i = 0; i < 4; i++) {
        float4 v;
        float* vp = (float*)&v;
#pragma unroll
        for (int j = 0; j < 4; j++)
            vp[j] = acc[i][j] + __ldg(crow + n0 + (tc << 2) + j);
        *(float4*)(gv + (size_t)(m0 + (tr << 2) + i) * H2 + n0 + (tc << 2)) = v;
    }
}

// ---- elementwise split of an f32 array ------------------------------------------
__global__ void split_plain_kernel(const float* __restrict__ src,
                                   __nv_bfloat16* __restrict__ D0,
                                   __nv_bfloat16* __restrict__ D1) {
    int idx = blockIdx.x * blockDim.x + threadIdx.x;
    float4 v = *(const float4*)(src + (size_t)idx * 4);
    __nv_bfloat16 a0[4], a1[4];
    split2(v.x, a0[0], a1[0]);
    split2(v.y, a0[1], a1[1]);
    split2(v.z, a0[2], a1[2]);
    split2(v.w, a0[3], a1[3]);
    *(uint2*)(D0 + (size_t)idx * 4) = *(uint2*)a0;
    *(uint2*)(D1 + (size_t)idx * 4) = *(uint2*)a1;
}

// ---- z = (1+eps)h + agg, split to bf16x2 ----------------------------------------
__global__ void split_z_kernel(const float* __restrict__ h,
                               const float* __restrict__ agg,
                               const float* __restrict__ epsp,
                               __nv_bfloat16* __restrict__ Z0,
                               __nv_bfloat16* __restrict__ Z1) {
    int idx = blockIdx.x * blockDim.x + threadIdx.x;
    float c0 = 1.0f + __ldg(epsp);
    float4 hv = *(const float4*)(h + (size_t)idx * 4);
    float4 gvv = *(const float4*)(agg + (size_t)idx * 4);
    float z[4] = { fmaf(c0, hv.x, gvv.x), fmaf(c0, hv.y, gvv.y),
                   fmaf(c0, hv.z, gvv.z), fmaf(c0, hv.w, gvv.w) };
    __nv_bfloat16 a0[4], a1[4];
#pragma unroll
    for (int q = 0; q < 4; q++) split2(z[q], a0[q], a1[q]);
    *(uint2*)(Z0 + (size_t)idx * 4) = *(uint2*)a0;
    *(uint2*)(Z1 + (size_t)idx * 4) = *(uint2*)a1;
}

// ---------------- atom encoder -----------------------------------------------------
__global__ void atom_kernel(const int* __restrict__ x,
                            const float* __restrict__ emb,
                            float* __restrict__ h) {
    int idx = blockIdx.x * blockDim.x + threadIdx.x;
    int n = idx >> 5;
    int c = (idx & 31) << 2;
    float4 acc = make_float4(0.f, 0.f, 0.f, 0.f);
#pragma unroll
    for (int f = 0; f < FA; f++) {
        int v = x[n * FA + f];
        float4 e = *(const float4*)(emb + ((size_t)(f * VA + v) * H) + c);
        acc.x += e.x; acc.y += e.y; acc.z += e.z; acc.w += e.w;
    }
    *(float4*)(h + (size_t)n * H + c) = acc;
}

__global__ void vninit_kernel(const float* __restrict__ vn_emb,
                              float* __restrict__ vn) {
    int idx = blockIdx.x * blockDim.x + threadIdx.x;
    int g = idx >> 5;
    int c = (idx & 31) << 2;
    *(float4*)(vn + (size_t)g * H + c) = *(const float4*)(vn_emb + c);
}

__global__ void addvn_kernel(float* __restrict__ h,
                             const float* __restrict__ vn,
                             const int* __restrict__ batch,
                             float* __restrict__ agg) {
    int idx = blockIdx.x * blockDim.x + threadIdx.x;
    int n = idx >> 5;
    int c = (idx & 31) << 2;
    int g = batch[n];
    float4 hv = *(float4*)(h + (size_t)n * H + c);
    float4 vv = *(const float4*)(vn + (size_t)g * H + c);
    hv.x += vv.x; hv.y += vv.y; hv.z += vv.z; hv.w += vv.w;
    *(float4*)(h + (size_t)n * H + c) = hv;
    *(float4*)(agg + (size_t)n * H + c) = make_float4(0.f, 0.f, 0.f, 0.f);
}

__global__ void edge_kernel(const int* __restrict__ ei,
                            const int* __restrict__ ea,
                            const float* __restrict__ bond,
                            const float* __restrict__ h,
                            float* __restrict__ agg) {
    __shared__ float tab[FB * VB * H];
    for (int i = threadIdx.x; i < FB * VB * H; i += blockDim.x) tab[i] = bond[i];
    __syncthreads();
    int e = (blockIdx.x * blockDim.x + threadIdx.x) >> 5;
    int lane = threadIdx.x & 31;
    int src = ei[e];
    int dst = ei[N_EDGES + e];
    int a0 = ea[e * 3 + 0], a1 = ea[e * 3 + 1], a2 = ea[e * 3 + 2];
    int c = lane << 2;
    float4 hv = *(const float4*)(h + (size_t)src * H + c);
    float4 e0 = *(const float4*)(tab + (0 * VB + a0) * H + c);
    float4 e1 = *(const float4*)(tab + (1 * VB + a1) * H + c);
    float4 e2 = *(const float4*)(tab + (2 * VB + a2) * H + c);
    float m0 = fmaxf(hv.x + e0.x + e1.x + e2.x, 0.f);
    float m1 = fmaxf(hv.y + e0.y + e1.y + e2.y, 0.f);
    float m2 = fmaxf(hv.z + e0.z + e1.z + e2.z, 0.f);
    float m3 = fmaxf(hv.w + e0.w + e1.w + e2.w, 0.f);
    red4(agg + (size_t)dst * H + c, m0, m1, m2, m3);
}

// ======== bf16x2 GEMM v6: tile 128x128, single accumulator, 3 products ===========
// 8 warps = 4m x 2n, warp tile 32x64. acc += A0B0 + A0B1 + A1B0.
#define BK 32
#define A_LD 40
#define B_LD 136
#define OFF_A0 0
#define OFF_A1 10240
#define OFF_B0 20480
#define OFF_B1 29184
#define STAGE  37888   // bytes per stage; x2 = 75776 (dynamic SMEM)

template <bool BN_RELU, bool OUT_F32, bool OUT_SPLIT, bool POOL>
__global__ __launch_bounds__(256, 2) void gemm3(
    const __nv_bfloat16* __restrict__ A0g, const __nv_bfloat16* __restrict__ A1g,
    const __nv_bfloat16* __restrict__ W0, const __nv_bfloat16* __restrict__ W1,
    const float* __restrict__ bias,
    const float* __restrict__ bng, const float* __restrict__ bnb,
    const float* __restrict__ bnm, const float* __restrict__ bnv,
    float* __restrict__ Cf,
    __nv_bfloat16* __restrict__ C0, __nv_bfloat16* __restrict__ C1,
    const float* __restrict__ gv, const int* __restrict__ batch,
    float* __restrict__ pooled,
    int M, int K, int Ncol) {
    extern __shared__ __align__(16) char smem[];

    const int tid = threadIdx.x;
    const int wid = tid >> 5;
    const int wm = wid & 3;            // 4 m-warps, 32 rows each
    const int wn = wid >> 2;           // 2 n-warps, 64 cols each
    const int m0 = blockIdx.x * 128;
    const int n0 = blockIdx.y * 128;

    const int arow = tid >> 1;
    const int ak = (tid & 1) << 4;
    const int grow = m0 + arow;

    wmma::fragment<wmma::accumulator, 16, 16, 16, float> acc[2][4];
#pragma unroll
    for (int mi = 0; mi < 2; mi++)
#pragma unroll
        for (int ni = 0; ni < 4; ni++) wmma::fill_fragment(acc[mi][ni], 0.0f);

    auto stage = [&](int kt, int buf) {
        char* base = smem + buf * STAGE;
        int gk = kt * BK + ak;
        size_t o = (size_t)grow * K + gk;
        int soff = (arow * A_LD + ak) * 2;
        cp16(base + OFF_A0 + soff, A0g + o);
        cp16(base + OFF_A0 + soff + 16, A0g + o + 8);
        cp16(base + OFF_A1 + soff, A1g + o);
        cp16(base + OFF_A1 + soff + 16, A1g + o + 8);
        // B: 2 splits x 32 rows x 128 cols = 1024 16B-chunks, 4 per thread
#pragma unroll
        for (int c = tid; c < 1024; c += 256) {
            int sp = c >> 9, rem = c & 511, r = rem >> 4, ch = rem & 15;
            size_t go = (size_t)(kt * BK + r) * Ncol + n0 + ch * 8;
            const __nv_bfloat16* src = (sp == 0) ? (W0 + go) : (W1 + go);
            cp16(base + OFF_B0 + sp * 8704 + (r * B_LD + ch * 8) * 2, src);
        }
        asm volatile("cp.async.commit_group;\n" ::);
    };

    const int KT = K / BK;
    stage(0, 0);
    for (int kt = 0; kt < KT; kt++) {
        if (kt + 1 < KT) {
            stage(kt + 1, (kt + 1) & 1);
            asm volatile("cp.async.wait_group 1;\n" ::);
        } else {
            asm volatile("cp.async.wait_group 0;\n" ::);
        }
        __syncthreads();
        char* base = smem + (kt & 1) * STAGE;
        const __nv_bfloat16* Ab0 = (const __nv_bfloat16*)(base + OFF_A0);
        const __nv_bfloat16* Ab1 = (const __nv_bfloat16*)(base + OFF_A1);
        const __nv_bfloat16* Bb0 = (const __nv_bfloat16*)(base + OFF_B0);
        const __nv_bfloat16* Bb1 = (const __nv_bfloat16*)(base + OFF_B1);

#pragma unroll
        for (int kk = 0; kk < 2; kk++) {
            wmma::fragment<wmma::matrix_a, 16, 16, 16, __nv_bfloat16, wmma::row_major>
                a0[2], a1[2];
#pragma unroll
            for (int mi = 0; mi < 2; mi++) {
                int ao = (wm * 32 + mi * 16) * A_LD + kk * 16;
                wmma::load_matrix_sync(a0[mi], Ab0 + ao, A_LD);
                wmma::load_matrix_sync(a1[mi], Ab1 + ao, A_LD);
            }
#pragma unroll
            for (int ni = 0; ni < 4; ni++) {
                wmma::fragment<wmma::matrix_b, 16, 16, 16, __nv_bfloat16, wmma::row_major> b0, b1;
                int bo = (kk * 16) * B_LD + wn * 64 + ni * 16;
                wmma::load_matrix_sync(b0, Bb0 + bo, B_LD);
                wmma::load_matrix_sync(b1, Bb1 + bo, B_LD);
#pragma unroll
                for (int mi = 0; mi < 2; mi++) {
                    wmma::mma_sync(acc[mi][ni], a0[mi], b0, acc[mi][ni]);
                    wmma::mma_sync(acc[mi][ni], a0[mi], b1, acc[mi][ni]);
                    wmma::mma_sync(acc[mi][ni], a1[mi], b0, acc[mi][ni]);
                }
            }
        }
        __syncthreads();
    }

    // park in SMEM (aliases stage buffers; Cs = 128x128 f32 = 64KB <= 75776)
    float* Cs = (float*)smem;
#pragma unroll
    for (int mi = 0; mi < 2; mi++)
#pragma unroll
        for (int ni = 0; ni < 4; ni++)
            wmma::store_matrix_sync(&Cs[(wm * 32 + mi * 16) * 128 + wn * 64 + ni * 16],
                                    acc[mi][ni], 128, wmma::mem_row_major);
    __syncthreads();

    const int erow = tid >> 1;
    const int ecb = (tid & 1) << 6;          // 0 or 64
    int bg = 0;
    const float* gvrow = nullptr;
    if (POOL) {
        bg = batch[m0 + erow];
        gvrow = gv + (size_t)bg * H2;
    }
    const size_t rowoff = (size_t)(m0 + erow) * Ncol;
#pragma unroll
    for (int j = 0; j < 64; j += 4) {
        float y[4];
#pragma unroll
        for (int q = 0; q < 4; q++) {
            int col = n0 + ecb + j + q;
            float v = Cs[erow * 128 + ecb + j + q];
            if (POOL) {
                float s = __ldg(bng + col) * rsqrtf(__ldg(bnv + col) + 1e-5f);
                float off = __ldg(bnb + col) - __ldg(bnm + col) * s;
                y[q] = fmaxf(fmaf(v + __ldg(gvrow + col), s, off), 0.0f);
            } else if (BN_RELU) {
                float s = __ldg(bng + col) * rsqrtf(__ldg(bnv + col) + 1e-5f);
                float off = (__ldg(bias + col) - __ldg(bnm + col)) * s + __ldg(bnb + col);
                y[q] = fmaxf(fmaf(v, s, off), 0.0f);
            } else {
                y[q] = v + __ldg(bias + col);
            }
        }
        if (POOL) {
            red4(pooled + (size_t)bg * H2 + n0 + ecb + j, y[0], y[1], y[2], y[3]);
        } else {
            size_t o = rowoff + n0 + ecb + j;
            if (OUT_F32)
                *(float4*)(Cf + o) = make_float4(y[0], y[1], y[2], y[3]);
            if (OUT_SPLIT) {
                __nv_bfloat16 s0[4], s1[4];
#pragma unroll
                for (int q = 0; q < 4; q++) split2(y[q], s0[q], s1[q]);
                *(uint2*)(C0 + o) = *(uint2*)s0;
                *(uint2*)(C1 + o) = *(uint2*)s1;
            }
        }
    }
}

// ---------------- zero pooled -------------------------------------------------------
__global__ void zero_pooled_kernel(float4* __restrict__ p) {
    int idx = blockIdx.x * blockDim.x + threadIdx.x;
    p[idx] = make_float4(0.f, 0.f, 0.f, 0.f);
}

__global__ void final_kernel(const float* __restrict__ vn,
                             const float* __restrict__ pW1,
                             const float* __restrict__ pb1,
                             const float* __restrict__ pW2,
                             const float* __restrict__ pb2,
                             float* __restrict__ out) {
    int g = blockIdx.x;
    int j = threadIdx.x;
    __shared__ float vrow[H];
    vrow[j] = vn[(size_t)g * H + j];
    __syncthreads();
    float acc = pb1[j];
#pragma unroll 8
    for (int k = 0; k < H; k++) acc = fmaf(vrow[k], __ldg(pW1 + k * H + j), acc);
    float val = fmaxf(acc, 0.0f) * __ldg(pW2 + j);
#pragma unroll
    for (int o = 16; o > 0; o >>= 1) val += __shfl_down_sync(0xffffffffu, val, o);
    __shared__ float part[4];
    if ((j & 31) == 0) part[j >> 5] = val;
    __syncthreads();
    if (j == 0) {
        float s = part[0] + part[1] + part[2] + part[3] + pb2[0];
        out[g] = fminf(fmaxf(s, 0.0f), 50.0f);
    }
}

// ---------------- launch ---------------------------------------------------------------
extern "C" void kernel_launch(void* const* d_in, const int* in_sizes, int n_in,
                              void* d_out, int out_size) {
    const int* x          = (const int*)d_in[0];
    const int* edge_index = (const int*)d_in[1];
    const int* edge_attr  = (const int*)d_in[2];
    const int* batch      = (const int*)d_in[3];
    const float* atom_emb  = (const float*)d_in[4];
    const float* vn_emb    = (const float*)d_in[5];
    const float* bond_emb  = (const float*)d_in[6];
    const float* conv_eps  = (const float*)d_in[7];
    const float* conv_W1   = (const float*)d_in[8];
    const float* conv_b1   = (const float*)d_in[9];
    const float* conv_bn_g = (const float*)d_in[10];
    const float* conv_bn_b = (const float*)d_in[11];
    const float* conv_bn_m = (const float*)d_in[12];
    const float* conv_bn_v = (const float*)d_in[13];
    const float* conv_W2   = (const float*)d_in[14];
    const float* conv_b2   = (const float*)d_in[15];
    const float* vn1_W  = (const float*)d_in[16];
    const float* vn1_b  = (const float*)d_in[17];
    const float* vn1_g  = (const float*)d_in[18];
    const float* vn1_be = (const float*)d_in[19];
    const float* vn1_m  = (const float*)d_in[20];
    const float* vn1_v  = (const float*)d_in[21];
    const float* vn2_W  = (const float*)d_in[22];
    const float* vn2_b  = (const float*)d_in[23];
    const float* vn2_g  = (const float*)d_in[24];
    const float* vn2_be = (const float*)d_in[25];
    const float* vn2_m  = (const float*)d_in[26];
    const float* vn2_v  = (const float*)d_in[27];
    const float* pW1 = (const float*)d_in[28];
    const float* pb1 = (const float*)d_in[29];
    const float* pW2 = (const float*)d_in[30];
    const float* pb2 = (const float*)d_in[31];
    float* out = (float*)d_out;

    float *h, *agg, *vn, *pooled, *gv, *crow;
    __nv_bfloat16 *w0, *w1, *m0p, *m1p;
    __nv_bfloat16 *sZ0, *sZ1, *sT0, *sT1, *sP0, *sP1;
    cudaGetSymbolAddress((void**)&h, g_h);
    cudaGetSymbolAddress((void**)&agg, g_agg);
    cudaGetSymbolAddress((void**)&vn, g_vn);
    cudaGetSymbolAddress((void**)&pooled, g_pooled);
    cudaGetSymbolAddress((void**)&gv, g_gv);
    cudaGetSymbolAddress((void**)&crow, g_crow);
    cudaGetSymbolAddress((void**)&w0, g_w0);
    cudaGetSymbolAddress((void**)&w1, g_w1);
    cudaGetSymbolAddress((void**)&m0p, g_m0);
    cudaGetSymbolAddress((void**)&m1p, g_m1);
    cudaGetSymbolAddress((void**)&sZ0, g_Z0); cudaGetSymbolAddress((void**)&sZ1, g_Z1);
    cudaGetSymbolAddress((void**)&sT0, g_T0); cudaGetSymbolAddress((void**)&sT1, g_T1);
    cudaGetSymbolAddress((void**)&sP0, g_P0); cudaGetSymbolAddress((void**)&sP1, g_P1);

    const int DSM = 2 * STAGE;
    cudaFuncSetAttribute(gemm3<true,  false, true,  false>, cudaFuncAttributeMaxDynamicSharedMemorySize, DSM);
    cudaFuncSetAttribute(gemm3<false, true,  false, false>, cudaFuncAttributeMaxDynamicSharedMemorySize, DSM);
    cudaFuncSetAttribute(gemm3<true,  false, false, true >, cudaFuncAttributeMaxDynamicSharedMemorySize, DSM);
    cudaFuncSetAttribute(gemm3<true,  true,  false, false>, cudaFuncAttributeMaxDynamicSharedMemorySize, DSM);

    const int OFF_W1 = 0;        // 128x256
    const int OFF_W2 = 32768;    // 256x128
    const int OFF_V2 = 65536;    // 256x128
    for (int i = 0; i < LAYERS; i++) {
        size_t off = (size_t)i * WT_L;
        wconv2_kernel<<<(H * H2 + 255) / 256, 256>>>(
            conv_W1 + (size_t)i * H * H2, w0 + off + OFF_W1, w1 + off + OFF_W1, H * H2);
        wconv2_kernel<<<(H2 * H + 255) / 256, 256>>>(
            conv_W2 + (size_t)i * H2 * H, w0 + off + OFF_W2, w1 + off + OFF_W2, H2 * H);
        wconv2_kernel<<<(H2 * H + 255) / 256, 256>>>(
            vn2_W + (size_t)i * H2 * H, w0 + off + OFF_V2, w1 + off + OFF_V2, H2 * H);
        compose_kernel<<<H2, H2>>>(conv_W2 + (size_t)i * H2 * H,
                                   vn1_W + (size_t)i * H2 * H2,
                                   m0p + (size_t)i * H2 * H2, m1p + (size_t)i * H2 * H2);
        crow_kernel<<<1, H2>>>(vn1_W + (size_t)i * H2 * H2, conv_b2 + i * H,
                               vn1_b + i * H2, crow + (size_t)i * H2);
    }

    atom_kernel<<<(N_NODES * 32) / 256, 256>>>(x, atom_emb, h);
    vninit_kernel<<<(N_GRAPHS * 32) / 256, 256>>>(vn_emb, vn);

    for (int i = 0; i < LAYERS; i++) {
        size_t off = (size_t)i * WT_L;
        addvn_kernel<<<(N_NODES * 32) / 256, 256>>>(h, vn, batch, agg);
        edge_kernel<<<N_EDGES / 8, 256>>>(edge_index, edge_attr,
                                          bond_emb + (size_t)i * FB * VB * H, h, agg);
        split_z_kernel<<<(N_NODES * H / 4) / 256, 256>>>(h, agg, conv_eps + i, sZ0, sZ1);
        // conv1: T(splits) = relu(bn(z @ W1 + b1))   [N,256]
        gemm3<true, false, true, false><<<dim3(N_NODES / 128, 2), 256, DSM>>>(
            sZ0, sZ1, w0 + off + OFF_W1, w1 + off + OFF_W1,
            conv_b1 + i * H2, conv_bn_g + i * H2, conv_bn_b + i * H2,
            conv_bn_m + i * H2, conv_bn_v + i * H2,
            nullptr, sT0, sT1, nullptr, nullptr, nullptr, N_NODES, H, H2);
        // conv2: h = T @ W2 + b2  (f32 only)          [N,128]
        gemm3<false, true, false, false><<<dim3(N_NODES / 128, 1), 256, DSM>>>(
            sT0, sT1, w0 + off + OFF_W2, w1 + off + OFF_W2,
            conv_b2 + i * H, nullptr, nullptr, nullptr, nullptr,
            h, nullptr, nullptr, nullptr, nullptr, nullptr, N_NODES, H2, H);
        // gv = vn @ V1_top + crow                      [G,256]
        gvn_kernel<<<dim3(N_GRAPHS / 64, H2 / 64), 256>>>(
            vn, vn1_W + (size_t)i * H2 * H2, crow + (size_t)i * H2, gv);
        // pooled = segsum(relu(bn(T@M2 + gv[batch])))   (fused vn1 + pool)
        zero_pooled_kernel<<<(N_GRAPHS * H2 / 4) / 256, 256>>>((float4*)pooled);
        gemm3<true, false, false, true><<<dim3(N_NODES / 128, 2), 256, DSM>>>(
            sT0, sT1, m0p + (size_t)i * H2 * H2, m1p + (size_t)i * H2 * H2,
            nullptr, vn1_g + i * H2, vn1_be + i * H2, vn1_m + i * H2, vn1_v + i * H2,
            nullptr, nullptr, nullptr, gv, batch, pooled, N_NODES, H2, H2);
        // split pooled, then vn2: vn = relu(bn(pooled @ V2 + b))  [G,128] f32 only
        split_plain_kernel<<<(N_GRAPHS * H2 / 4) / 256, 256>>>(pooled, sP0, sP1);
        gemm3<true, true, false, false><<<dim3(N_GRAPHS / 128, 1), 256, DSM>>>(
            sP0, sP1, w0 + off + OFF_V2, w1 + off + OFF_V2,
            vn2_b + i * H, vn2_g + i * H, vn2_be + i * H, vn2_m + i * H, vn2_v + i * H,
            vn, nullptr, nullptr, nullptr, nullptr, nullptr, N_GRAPHS, H2, H);
    }
    final_kernel<<<N_GRAPHS, 128>>>(vn, pW1, pb1, pW2, pb2, out);
}